// round 3
// baseline (speedup 1.0000x reference)
#include <cuda_runtime.h>
#include <math.h>
#include <cfloat>

#define BB 8
#define QQ 2048
#define GG 128
#define CC 512
#define NT 256
#define COLS_PT (QQ/NT)      // 8
#define MAXC 256
#define MAXPATH 132          // path visits only matched cols (+ final) <= GG+2

// ---------------- device scratch (no allocation allowed) ----------------
__device__ float g_ct[BB*GG*QQ];   // transposed cost: CT[b][g][q]  (8 MB)
__device__ int   g_labels[BB*GG];
__device__ int   g_na[BB];

// ---------------- prep: normalize int inputs (int32 vs int64 on disk) ----
__global__ void prep_kernel(const int* __restrict__ lab_raw,
                            const int* __restrict__ na_raw) {
    __shared__ int nzl, nzn;
    int t = threadIdx.x;
    if (t == 0) { nzl = 0; nzn = 0; }
    __syncthreads();
    for (int k = t; k < (BB*GG)/2; k += blockDim.x)
        if (lab_raw[2*k+1] != 0) atomicExch(&nzl, 1);
    for (int k = t; k < BB/2; k += blockDim.x)
        if (na_raw[2*k+1] != 0) atomicExch(&nzn, 1);
    __syncthreads();
    bool l64 = (nzl == 0), n64 = (nzn == 0);
    for (int k = t; k < BB*GG; k += blockDim.x)
        g_labels[k] = l64 ? lab_raw[2*k] : lab_raw[k];
    if (t < BB)
        g_na[t] = n64 ? na_raw[2*t] : na_raw[t];
}

// ---------------- cost: focal-class gather + weighted sum ---------------
__global__ void cost_kernel(const float* __restrict__ sem,
                            const float* __restrict__ center,
                            const float* __restrict__ sizes,
                            const float* __restrict__ gious,
                            float* __restrict__ fc) {
    int q = blockIdx.x, b = blockIdx.y, g = threadIdx.x;
    int lab = g_labels[b*GG + g];
    float s = sem[((size_t)(b*QQ + q))*CC + lab];
    // XLA lowers lax.logistic as 0.5 + 0.5*tanh(0.5*x)
    float p = 0.5f + 0.5f * tanhf(0.5f * s);
    float pos = 0.25f * (1.0f - p) * (1.0f - p) * (-logf(p + 1e-8f));
    float neg = 0.75f * p * p * (-log1pf(-(p - 1e-8f)));
    float diff = pos - neg;
    size_t idx = ((size_t)(b*QQ + q))*GG + g;
    fc[idx] = 2.0f*diff + 5.0f*center[idx] + 1.0f*sizes[idx] - 2.0f*gious[idx];
}

// ---------------- transpose fc[b][q][g] -> CT[b][g][q] ------------------
__global__ void transpose_kernel(const float* __restrict__ fc) {
    __shared__ float tile[32][33];
    int b = blockIdx.z;
    int q0 = blockIdx.x * 32, g0 = blockIdx.y * 32;
    int x = threadIdx.x;
    for (int r = threadIdx.y; r < 32; r += 8)
        tile[r][x] = fc[((size_t)(b*QQ + q0 + r))*GG + g0 + x];
    __syncthreads();
    for (int r = threadIdx.y; r < 32; r += 8)
        g_ct[((size_t)(b*GG + g0 + r))*QQ + q0 + x] = tile[x][r];
}

// --------- order-preserving uint key for float (monotone) ---------------
__device__ __forceinline__ unsigned fkey(float f) {
    unsigned u = __float_as_uint(f);
    return (u & 0x80000000u) ? ~u : (u | 0x80000000u);
}
__device__ __forceinline__ float finv(unsigned k) {
    unsigned u = (k & 0x80000000u) ? (k & 0x7fffffffu) : ~k;
    return __uint_as_float(u);
}

// ---------------- LSA: exact replica of the reference's algorithm -------
// Lazy-delta formulation: within one row search every scan reads only BASE
// u/v (deltas only touch path members, which are excluded from scans), so we
// record (column, delta_t) per step and replay the incremental updates
// bit-exactly in a parallel write-back at search end.
__global__ void __launch_bounds__(NT) lsa_kernel(float* __restrict__ out_inds,
                                                 float* __restrict__ out_mask) {
    __shared__ double v[QQ + 1];        // fp64 master potentials (base during a search)
    __shared__ float  vf[QQ + 1];       // fp32 shadow (-FLT_MAX sentinel = used)
    __shared__ double u[GG + 1];
    __shared__ short  p[QQ + 1];
    __shared__ unsigned short ulist[MAXPATH];
    __shared__ double sdelta[MAXPATH];
    __shared__ double cand_v[MAXC];
    __shared__ int    cand_j[MAXC];
    __shared__ int s_ncand, s_done, s_i0, s_cnt, s_bj;
    __shared__ double s_ui;
    __shared__ float  s_uif;

    int b = blockIdx.x;
    int tid = threadIdx.x;
    const float* CT = g_ct + (size_t)b * GG * QQ;

    int na = g_na[b];
    if (na < 0) na = 0;
    if (na > GG) na = GG;

    for (int j = tid; j <= QQ; j += NT) { v[j] = 0.0; vf[j] = 0.0f; p[j] = 0; }
    for (int j = tid; j <= GG; j += NT) u[j] = 0.0;
    __syncthreads();

    for (int i = 1; i <= na; i++) {
        if (tid == 0) {
            p[0] = (short)i;
            ulist[0] = 0;                // column 0 joins at step 0
            s_cnt = 1;
            s_i0 = i;
            s_ui = u[i];
            s_uif = (float)u[i];
            s_ncand = 0;
            s_done = 0;
        }
        __syncthreads();                 // (A) setup / write-back of prev search visible

        while (true) {
            // ---- scan + candidate post (single phase) ----
            const float* row = CT + (size_t)(s_i0 - 1) * QQ;
            float uif = s_uif;
            float r[COLS_PT], c[COLS_PT];
            #pragma unroll
            for (int k = 0; k < COLS_PT; k++) {
                int j = tid + 1 + k * NT;
                r[k] = row[j - 1];
                c[k] = (r[k] - uif) - vf[j];   // used cols: vf=-FLT_MAX => c=+huge
            }
            float m = c[0];
            #pragma unroll
            for (int k = 1; k < COLS_PT; k++) m = fminf(m, c[k]);
            unsigned wmin = __reduce_min_sync(0xffffffffu, fkey(m));
            float wm = finv(wmin);
            float thr = wm + fmaxf(1e-3f, 3e-6f * fabsf(wm));
            double uid = s_ui;
            #pragma unroll
            for (int k = 0; k < COLS_PT; k++) {
                if (c[k] <= thr) {
                    int j = tid + 1 + k * NT;
                    double cd = ((double)r[k] - uid) - v[j];
                    int slot = atomicAdd(&s_ncand, 1);
                    if (slot < MAXC) { cand_v[slot] = cd; cand_j[slot] = j; }
                }
            }
            __syncthreads();             // (B) candidates posted

            // ---- tid0: exact fp64 argmin over posted superset, O(1) setup ----
            if (tid == 0) {
                int nc = s_ncand; if (nc > MAXC) nc = MAXC;
                double best = DBL_MAX; int bj = 0x7fffffff;
                for (int s = 0; s < nc; s++) {
                    double cv = cand_v[s]; int cj = cand_j[s];
                    if (cv < best || (cv == best && cj < bj)) { best = cv; bj = cj; }
                }
                int cnt = s_cnt;
                sdelta[cnt - 1] = best;  // delta of iteration t = cnt-1
                if (p[bj] == 0) {
                    s_bj = bj;
                    s_done = 1;          // way==0 => single-step backtrack
                } else {
                    int i0 = p[bj];
                    s_i0 = i0;
                    s_ui = u[i0];        // base value (untouched during search)
                    s_uif = (float)u[i0];
                    vf[bj] = -FLT_MAX;   // mark used
                    ulist[cnt] = (unsigned short)bj;   // joins at step cnt
                    s_cnt = cnt + 1;
                    s_ncand = 0;
                }
            }
            __syncthreads();             // (C) hop state / done visible
            if (s_done) break;
        }

        // ---- parallel bit-exact write-back: entry k gets deltas k..cnt-1 ----
        {
            int cnt = s_cnt;
            if (tid < cnt) {
                int jj = ulist[tid];
                int ik = p[jj];
                double uu = u[ik];
                double vv = v[jj];
                for (int t = tid; t < cnt; t++) {
                    double d = sdelta[t];
                    uu += d;
                    vv -= d;
                }
                u[ik] = uu;
                v[jj] = vv;
                if (tid > 0) vf[jj] = (float)vv;   // restore shadow (col 0 unused)
            }
            if (tid == 0) p[s_bj] = (short)i;      // assign final unmatched column
        }
        __syncthreads();                 // order write-back before next search
    }

    // outputs: proposal j-1 matched to gt p[j]-1
    for (int j = tid + 1; j <= QQ; j += NT) {
        int pj = p[j];
        size_t o = (size_t)b * QQ + (j - 1);
        out_inds[o] = (pj > 0) ? (float)(pj - 1) : 0.0f;
        out_mask[o] = (pj > 0) ? 1.0f : 0.0f;
    }
}

// ---------------- launch ------------------------------------------------
extern "C" void kernel_launch(void* const* d_in, const int* in_sizes, int n_in,
                              void* d_out, int out_size) {
    const float* sem    = (const float*)d_in[0];
    const float* center = (const float*)d_in[1];
    const float* sizes  = (const float*)d_in[2];
    const float* gious  = (const float*)d_in[3];
    const int*   labels = (const int*)d_in[4];
    const int*   na     = (const int*)d_in[5];

    float* out      = (float*)d_out;
    float* out_inds = out;
    float* out_mask = out + (size_t)BB * QQ;
    float* fc       = out + (size_t)2 * BB * QQ;   // final_cost region

    prep_kernel<<<1, 512>>>(labels, na);
    cost_kernel<<<dim3(QQ, BB), GG>>>(sem, center, sizes, gious, fc);
    transpose_kernel<<<dim3(QQ/32, GG/32, BB), dim3(32, 8)>>>(fc);
    lsa_kernel<<<BB, NT>>>(out_inds, out_mask);
}

// round 4
// speedup vs baseline: 1.4872x; 1.4872x over previous
#include <cuda_runtime.h>
#include <math.h>
#include <cfloat>

#define BB 8
#define QQ 2048
#define GG 128
#define CC 512
#define NT 512
#define NW (NT/32)           // 16 warps
#define COLS_PT (QQ/NT)      // 4
#define MAXC 64
#define MAXPATH 136          // path cols: col0 + <=G matched + final

// ---------------- device scratch (no allocation allowed) ----------------
__device__ float g_ct[BB*GG*QQ];   // transposed cost: CT[b][g][q]  (8 MB)
__device__ int   g_labels[BB*GG];
__device__ int   g_na[BB];

// ---------------- prep: normalize int inputs (int32 vs int64 on disk) ----
__global__ void prep_kernel(const int* __restrict__ lab_raw,
                            const int* __restrict__ na_raw) {
    __shared__ int nzl, nzn;
    int t = threadIdx.x;
    if (t == 0) { nzl = 0; nzn = 0; }
    __syncthreads();
    for (int k = t; k < (BB*GG)/2; k += blockDim.x)
        if (lab_raw[2*k+1] != 0) atomicExch(&nzl, 1);
    for (int k = t; k < BB/2; k += blockDim.x)
        if (na_raw[2*k+1] != 0) atomicExch(&nzn, 1);
    __syncthreads();
    bool l64 = (nzl == 0), n64 = (nzn == 0);
    for (int k = t; k < BB*GG; k += blockDim.x)
        g_labels[k] = l64 ? lab_raw[2*k] : lab_raw[k];
    if (t < BB)
        g_na[t] = n64 ? na_raw[2*t] : na_raw[t];
}

// ---------------- cost: focal-class gather + weighted sum ---------------
__global__ void cost_kernel(const float* __restrict__ sem,
                            const float* __restrict__ center,
                            const float* __restrict__ sizes,
                            const float* __restrict__ gious,
                            float* __restrict__ fc) {
    int q = blockIdx.x, b = blockIdx.y, g = threadIdx.x;
    int lab = g_labels[b*GG + g];
    float s = sem[((size_t)(b*QQ + q))*CC + lab];
    // XLA lowers lax.logistic as 0.5 + 0.5*tanh(0.5*x)
    float p = 0.5f + 0.5f * tanhf(0.5f * s);
    float pos = 0.25f * (1.0f - p) * (1.0f - p) * (-logf(p + 1e-8f));
    float neg = 0.75f * p * p * (-log1pf(-(p - 1e-8f)));
    float diff = pos - neg;
    size_t idx = ((size_t)(b*QQ + q))*GG + g;
    fc[idx] = 2.0f*diff + 5.0f*center[idx] + 1.0f*sizes[idx] - 2.0f*gious[idx];
}

// ---------------- transpose fc[b][q][g] -> CT[b][g][q] ------------------
__global__ void transpose_kernel(const float* __restrict__ fc) {
    __shared__ float tile[32][33];
    int b = blockIdx.z;
    int q0 = blockIdx.x * 32, g0 = blockIdx.y * 32;
    int x = threadIdx.x;
    for (int r = threadIdx.y; r < 32; r += 8)
        tile[r][x] = fc[((size_t)(b*QQ + q0 + r))*GG + g0 + x];
    __syncthreads();
    for (int r = threadIdx.y; r < 32; r += 8)
        g_ct[((size_t)(b*GG + g0 + r))*QQ + q0 + x] = tile[x][r];
}

// --------- order-preserving uint key for float (monotone) ---------------
__device__ __forceinline__ unsigned fkey(float f) {
    unsigned u = __float_as_uint(f);
    return (u & 0x80000000u) ? ~u : (u | 0x80000000u);
}
__device__ __forceinline__ float finv(unsigned k) {
    unsigned u = (k & 0x80000000u) ? (k & 0x7fffffffu) : ~k;
    return __uint_as_float(u);
}

// ---------------- LSA: exact replica of the reference's algorithm -------
// fp32 scan -> GLOBAL min (warp REDUX + shared fold) -> fp64 verify of
// eps-candidates -> O(1) tid0 hop; (column, delta_t) recorded per step and
// replayed bit-exactly in a parallel write-back at search end.
__global__ void __launch_bounds__(NT) lsa_kernel(float* __restrict__ out_inds,
                                                 float* __restrict__ out_mask) {
    __shared__ double v[QQ + 1];        // fp64 master potentials (base during a search)
    __shared__ float  vf[QQ + 1];       // fp32 shadow (-FLT_MAX sentinel = used)
    __shared__ double u[GG + 1];
    __shared__ short  p[QQ + 1];
    __shared__ unsigned short ulist[MAXPATH];
    __shared__ double sdelta[MAXPATH];
    __shared__ unsigned swk[NW];        // per-warp min keys
    __shared__ double cand_v[MAXC];
    __shared__ int    cand_j[MAXC];
    __shared__ int s_ncand, s_done, s_i0, s_cnt, s_bj;
    __shared__ double s_ui;
    __shared__ float  s_uif;

    int b = blockIdx.x;
    int tid = threadIdx.x;
    int lane = tid & 31, wid = tid >> 5;
    const float* CT = g_ct + (size_t)b * GG * QQ;

    int na = g_na[b];
    if (na < 0) na = 0;
    if (na > GG) na = GG;

    for (int j = tid; j <= QQ; j += NT) { v[j] = 0.0; vf[j] = 0.0f; p[j] = 0; }
    for (int j = tid; j <= GG; j += NT) u[j] = 0.0;
    __syncthreads();

    for (int i = 1; i <= na; i++) {
        if (tid == 0) {
            p[0] = (short)i;
            ulist[0] = 0;                // column 0 joins at step 0
            s_cnt = 1;
            s_i0 = i;
            s_ui = u[i];
            s_uif = (float)u[i];
            s_ncand = 0;
            s_done = 0;
        }
        __syncthreads();                 // (A) setup / prev write-back visible

        while (true) {
            // ---- phase 1: fp32 scan + per-warp min ----
            const float* row = CT + (size_t)(s_i0 - 1) * QQ;
            float uif = s_uif;
            float r0, r1, r2, r3, c0, c1, c2, c3;
            {
                int j = tid + 1;
                r0 = row[j - 1];          r1 = row[j - 1 + NT];
                r2 = row[j - 1 + 2*NT];   r3 = row[j - 1 + 3*NT];
                c0 = (r0 - uif) - vf[j];
                c1 = (r1 - uif) - vf[j + NT];
                c2 = (r2 - uif) - vf[j + 2*NT];
                c3 = (r3 - uif) - vf[j + 3*NT];
            }
            float m = fminf(fminf(c0, c1), fminf(c2, c3));
            unsigned wk = __reduce_min_sync(0xffffffffu, fkey(m));
            if (lane == 0) swk[wid] = wk;
            __syncthreads();             // (B1) warp mins visible

            // ---- phase 2: fold global min locally, post fp64 candidates ----
            unsigned gk = swk[0];
            #pragma unroll
            for (int w = 1; w < NW; w++) gk = umin(gk, swk[w]);
            float thr = finv(gk) + 1e-3f;          // >=20x worst-case fp32 error
            if (m <= thr) {                        // fast reject for most threads
                double uid = s_ui;
                if (c0 <= thr) {
                    int j = tid + 1;
                    double cd = ((double)r0 - uid) - v[j];
                    int slot = atomicAdd(&s_ncand, 1);
                    if (slot < MAXC) { cand_v[slot] = cd; cand_j[slot] = j; }
                }
                if (c1 <= thr) {
                    int j = tid + 1 + NT;
                    double cd = ((double)r1 - uid) - v[j];
                    int slot = atomicAdd(&s_ncand, 1);
                    if (slot < MAXC) { cand_v[slot] = cd; cand_j[slot] = j; }
                }
                if (c2 <= thr) {
                    int j = tid + 1 + 2*NT;
                    double cd = ((double)r2 - uid) - v[j];
                    int slot = atomicAdd(&s_ncand, 1);
                    if (slot < MAXC) { cand_v[slot] = cd; cand_j[slot] = j; }
                }
                if (c3 <= thr) {
                    int j = tid + 1 + 3*NT;
                    double cd = ((double)r3 - uid) - v[j];
                    int slot = atomicAdd(&s_ncand, 1);
                    if (slot < MAXC) { cand_v[slot] = cd; cand_j[slot] = j; }
                }
            }
            __syncthreads();             // (B2) candidates posted

            // ---- phase 3: tid0 exact argmin + O(1) hop setup ----
            if (tid == 0) {
                int nc = s_ncand; if (nc > MAXC) nc = MAXC;
                double best = DBL_MAX; int bj = 0x7fffffff;
                for (int s = 0; s < nc; s++) {
                    double cv = cand_v[s]; int cj = cand_j[s];
                    if (cv < best || (cv == best && cj < bj)) { best = cv; bj = cj; }
                }
                int cnt = s_cnt;
                sdelta[cnt - 1] = best;  // delta of step t = cnt-1
                if (p[bj] == 0) {
                    s_bj = bj;
                    s_done = 1;          // way==0 => single-step backtrack
                } else {
                    int i0 = p[bj];
                    s_i0 = i0;
                    s_ui = u[i0];        // base value (untouched during search)
                    s_uif = (float)u[i0];
                    vf[bj] = -FLT_MAX;   // mark used
                    ulist[cnt] = (unsigned short)bj;   // joins at step cnt
                    s_cnt = cnt + 1;
                    s_ncand = 0;
                }
            }
            __syncthreads();             // (B3) hop state visible
            if (s_done) break;
        }

        // ---- parallel bit-exact write-back: entry k gets deltas k..cnt-1 ----
        {
            int cnt = s_cnt;
            if (tid < cnt) {
                int jj = ulist[tid];
                int ik = p[jj];
                double uu = u[ik];
                double vv = v[jj];
                for (int t = tid; t < cnt; t++) {
                    double d = sdelta[t];
                    uu += d;
                    vv -= d;
                }
                u[ik] = uu;
                v[jj] = vv;
                if (tid > 0) vf[jj] = (float)vv;   // restore shadow (col 0 has none)
            }
            if (tid == 0) p[s_bj] = (short)i;      // assign final unmatched column
        }
        __syncthreads();                 // order write-back before next search
    }

    // outputs: proposal j-1 matched to gt p[j]-1
    for (int j = tid + 1; j <= QQ; j += NT) {
        int pj = p[j];
        size_t o = (size_t)b * QQ + (j - 1);
        out_inds[o] = (pj > 0) ? (float)(pj - 1) : 0.0f;
        out_mask[o] = (pj > 0) ? 1.0f : 0.0f;
    }
}

// ---------------- launch ------------------------------------------------
extern "C" void kernel_launch(void* const* d_in, const int* in_sizes, int n_in,
                              void* d_out, int out_size) {
    const float* sem    = (const float*)d_in[0];
    const float* center = (const float*)d_in[1];
    const float* sizes  = (const float*)d_in[2];
    const float* gious  = (const float*)d_in[3];
    const int*   labels = (const int*)d_in[4];
    const int*   na     = (const int*)d_in[5];

    float* out      = (float*)d_out;
    float* out_inds = out;
    float* out_mask = out + (size_t)BB * QQ;
    float* fc       = out + (size_t)2 * BB * QQ;   // final_cost region

    prep_kernel<<<1, 512>>>(labels, na);
    cost_kernel<<<dim3(QQ, BB), GG>>>(sem, center, sizes, gious, fc);
    transpose_kernel<<<dim3(QQ/32, GG/32, BB), dim3(32, 8)>>>(fc);
    lsa_kernel<<<BB, NT>>>(out_inds, out_mask);
}